// round 15
// baseline (speedup 1.0000x reference)
#include <cuda_runtime.h>
#include <cuda_fp16.h>
#include <cstdint>

// ---------------------------------------------------------------------------
// ChannelMultiHeadAttention, fp32 in/out, fp16 tensor-core compute (m16n8k16).
//   energy = x A x^T + xu1 1^T + 1 xu2^T + c0,  A = Wq^T Wk
//   out    = att @ v + bv,  v = x @ Wv^T   (computed as vT C-frags)
// R15: attn compute identical to R9/R14 (best measured). Prep chain compressed:
//      ONE fused prep kernel (direct packing, no g_Af intermediate) + PDL
//      (programmatic dependent launch) so attn's independent prologue (x-tile
//      loads) overlaps prep execution; grid-sync before touching packed data.
// ---------------------------------------------------------------------------

#define FULLMASK 0xffffffffu

// Packed B-frags of [A | u1 u2 | 0pad]: entry[(k0*4+tq)*84 + e] =
//   {h2(A[16k0+2tq][e], A[16k0+2tq+1][e]), h2(A[16k0+2tq+8][e], A[16k0+2tq+9][e])}
__device__ uint2  g_PA[16 * 84];
// Packed A-frags of Wv: entry[(mt*8+q)*36 + cp] =
//   {h2(Wv[16mt+q][2cp], [2cp+1]), h2(Wv[16mt+q+8][2cp], [2cp+1])}
__device__ uint2  g_PW[32 * 36];
__device__ __half g_wch[256];     // wc padded 16x16 fp16
__device__ float  g_c0[1];

__device__ __forceinline__ uint32_t h2u(float a, float b) {
    __half2 h = __floats2half2_rn(a, b);
    return *(uint32_t*)&h;
}

__device__ __forceinline__ void mma16(float* d, uint32_t a0, uint32_t a1, uint32_t a2,
                                      uint32_t a3, uint32_t b0, uint32_t b1) {
    asm("mma.sync.aligned.m16n8k16.row.col.f32.f16.f16.f32 "
        "{%0,%1,%2,%3}, {%4,%5,%6,%7}, {%8,%9}, {%0,%1,%2,%3};"
        : "+f"(d[0]), "+f"(d[1]), "+f"(d[2]), "+f"(d[3])
        : "r"(a0), "r"(a1), "r"(a2), "r"(a3), "r"(b0), "r"(b1));
}

// ---------------------------------------------------------------------------
// Fused prep: blocks 0-7 pack P_A directly (4 smem dot-products per entry,
// no g_Af intermediate); blocks 8-11 pack P_W + wch + c0 (no A dependency).
// ---------------------------------------------------------------------------
__global__ void prep_kernel(const float* __restrict__ Wq, const float* __restrict__ bq,
                            const float* __restrict__ Wk, const float* __restrict__ bk,
                            const float* __restrict__ Wv, const float* __restrict__ wc) {
    int t = threadIdx.x, b = blockIdx.x;
    if (b < 8) {
        __shared__ float sWq[4096], sWk[4096];
        for (int i = t; i < 4096; i += 256) { sWq[i] = Wq[i]; sWk[i] = Wk[i]; }
        __syncthreads();

        int idx = b * 144 + t;              // 1152 PA entries, 144 per block
        if (t < 144) {
            int kq = idx / 72, e = idx % 72;
            int k0 = kq >> 2, tq = kq & 3;
            int db = 16 * k0 + 2 * tq;      // rows db, db+1, db+8, db+9 (even)
            float a0 = 0.f, a1 = 0.f, a2 = 0.f, a3 = 0.f;
            if (e < 64) {
                #pragma unroll 4
                for (int f = 0; f < 64; f++) {
                    float wk = sWk[f * 64 + e];
                    float2 q01 = *(const float2*)(sWq + f * 64 + db);
                    float2 q89 = *(const float2*)(sWq + f * 64 + db + 8);
                    a0 += q01.x * wk; a1 += q01.y * wk;
                    a2 += q89.x * wk; a3 += q89.y * wk;
                }
            } else if (e == 64) {           // u1 = Wq^T bk
                #pragma unroll 4
                for (int f = 0; f < 64; f++) {
                    float bkf = bk[f];
                    float2 q01 = *(const float2*)(sWq + f * 64 + db);
                    float2 q89 = *(const float2*)(sWq + f * 64 + db + 8);
                    a0 += q01.x * bkf; a1 += q01.y * bkf;
                    a2 += q89.x * bkf; a3 += q89.y * bkf;
                }
            } else if (e == 65) {           // u2 = Wk^T bq
                #pragma unroll 4
                for (int f = 0; f < 64; f++) {
                    float bqf = bq[f];
                    float2 k01 = *(const float2*)(sWk + f * 64 + db);
                    float2 k89 = *(const float2*)(sWk + f * 64 + db + 8);
                    a0 += k01.x * bqf; a1 += k01.y * bqf;
                    a2 += k89.x * bqf; a3 += k89.y * bqf;
                }
            }
            g_PA[kq * 84 + e] = make_uint2(h2u(a0, a1), h2u(a2, a3));
        }
    } else {
        // pack P_W (A-operand of vT GEMM = Wv row-major), 1152 entries
        for (int idx = (b - 8) * 256 + t; idx < 32 * 36; idx += 1024) {
            int r = idx / 36, cp = idx % 36;
            int mt = r >> 3, q = r & 7;
            uint2 u = make_uint2(0u, 0u);
            if (cp < 32) {
                int e0 = 16 * mt + q;
                u.x = h2u(Wv[e0 * 64 + 2 * cp], Wv[e0 * 64 + 2 * cp + 1]);
                u.y = h2u(Wv[(e0 + 8) * 64 + 2 * cp], Wv[(e0 + 8) * 64 + 2 * cp + 1]);
            }
            g_PW[idx] = u;
        }
        if (b == 8) {
            int a0 = t >> 4, c = t & 15;
            float v = (a0 < 14 && c < 14) ? wc[a0 * 14 + c] : 0.f;
            g_wch[t] = __float2half_rn(v);
            if (t == 0) {
                float cc = 0.f;
                for (int f = 0; f < 64; f++) cc += bq[f] * bk[f];
                g_c0[0] = cc;
            }
        }
    }
}

// ---------------------------------------------------------------------------
// Main: 1 warp = 1 pair, 8 warps/CTA, 8192 CTAs (exact). Compute = R9.
// Prologue reordered: prep-independent work first, then grid-dependency sync.
// smem: PA 10752 + PW 9216 + wc 768 + bv 256 + ln 128 + 8 x 2432 = 40576 B
// ---------------------------------------------------------------------------
static const int NW = 8;
static const int SMEM_BYTES = 10752 + 9216 + 768 + 256 + 128 + NW * 2432;  // 40576

__global__ __launch_bounds__(32 * NW, 3)
void attn_kernel(const float* __restrict__ x, const float* __restrict__ bv,
                 const float* __restrict__ lng, const float* __restrict__ lnb,
                 float* __restrict__ out) {
    extern __shared__ __align__(16) unsigned char smraw[];
    uint2*  sPA  = (uint2*)smraw;                    // 16*84
    uint2*  sPW  = sPA + 16 * 84;                    // 32*36
    __half* swch = (__half*)(sPW + 32 * 36);         // 16 x 24
    float*  sbv  = (float*)(swch + 384);             // 64
    float*  slg  = sbv + 64;                         // 16
    float*  slb  = slg + 16;                         // 16
    __half* stil = (__half*)(slb + 16);              // NW x 1216 halves

    const int t = threadIdx.x, w = t >> 5, l = t & 31;
    const int g = l >> 2, tg = l & 3;

    const size_t pair = (size_t)blockIdx.x * NW + w;
    __half* sx   = stil + w * 1216;          // 16 rows x 72 halves
    float*  sxu1 = (float*)(sx + 1152);      // 16
    float*  sxu2 = sxu1 + 16;                // 16

    // ---- prep-INDEPENDENT prologue: x tile + small consts ----
    if (t < 64) sbv[t] = bv[t];
    if (t < 16) {
        slg[t] = (t < 14) ? lng[t] : 0.f;
        slb[t] = (t < 14) ? lnb[t] : 0.f;
    }
    const float4* xg4 = (const float4*)(x + pair * 896);
    #pragma unroll
    for (int it = 0; it < 7; it++) {
        int k = l + 32 * it;
        float4 v = xg4[k];
        int row = k >> 4, c4 = k & 15;
        *(uint2*)(sx + row * 72 + c4 * 4) = make_uint2(h2u(v.x, v.y), h2u(v.z, v.w));
    }
    for (int i = l; i < 72; i += 32) ((uint32_t*)(sx + 14 * 72))[i] = 0u;

    // ---- wait for prep's device-global writes, then stage them ----
    cudaGridDependencySynchronize();
    for (int i = t; i < 16 * 84; i += 32 * NW) sPA[i] = g_PA[i];
    for (int i = t; i < 32 * 36; i += 32 * NW) sPW[i] = g_PW[i];
    if (t < 256) swch[(t >> 4) * 24 + (t & 15)] = g_wch[t];
    const float c0v = g_c0[0];
    __syncthreads();

    // ---- Y = x @ [A | u1 u2]  (4 k0 x 9 n0 = 36 MMAs) ----
    float dY[9][4] = {};
    #pragma unroll
    for (int k0 = 0; k0 < 4; k0++) {
        uint32_t a0 = *(const uint32_t*)(sx + g * 72 + k0 * 16 + 2 * tg);
        uint32_t a1 = *(const uint32_t*)(sx + (g + 8) * 72 + k0 * 16 + 2 * tg);
        uint32_t a2 = *(const uint32_t*)(sx + g * 72 + k0 * 16 + 2 * tg + 8);
        uint32_t a3 = *(const uint32_t*)(sx + (g + 8) * 72 + k0 * 16 + 2 * tg + 8);
        const uint2* pa = sPA + (k0 * 4 + tg) * 84 + g;
        #pragma unroll
        for (int n0 = 0; n0 < 9; n0++) {
            uint2 b = pa[n0 * 8];
            mma16(dY[n0], a0, a1, a2, a3, b.x, b.y);
        }
    }
    // dY[8] cols 64-71: tg==0 lanes hold (xu1, xu2) for rows g, g+8
    if (tg == 0) {
        sxu1[g] = dY[8][0]; sxu2[g] = dY[8][1];
        sxu1[g + 8] = dY[8][2]; sxu2[g + 8] = dY[8][3];
    }

    // ---- energy = y @ x^T  (8 MMAs); y A-frags are lane-local packs ----
    float e[2][4] = {};
    #pragma unroll
    for (int k0 = 0; k0 < 4; k0++) {
        uint32_t a0 = h2u(dY[2 * k0][0], dY[2 * k0][1]);
        uint32_t a1 = h2u(dY[2 * k0][2], dY[2 * k0][3]);
        uint32_t a2 = h2u(dY[2 * k0 + 1][0], dY[2 * k0 + 1][1]);
        uint32_t a3 = h2u(dY[2 * k0 + 1][2], dY[2 * k0 + 1][3]);
        #pragma unroll
        for (int nt = 0; nt < 2; nt++) {
            uint32_t b0 = *(const uint32_t*)(sx + (nt * 8 + g) * 72 + k0 * 16 + 2 * tg);
            uint32_t b1 = *(const uint32_t*)(sx + (nt * 8 + g) * 72 + k0 * 16 + 2 * tg + 8);
            mma16(e[nt], a0, a1, a2, a3, b0, b1);
        }
    }
    __syncwarp();   // sxu stores visible
    float et[2][4];
    {
        float xg0 = sxu1[g] + c0v, xg8 = sxu1[g + 8] + c0v;
        #pragma unroll
        for (int nt = 0; nt < 2; nt++) {
            int j0 = nt * 8 + 2 * tg;
            float u0 = sxu2[j0], u1v = sxu2[j0 + 1];
            et[nt][0] = e[nt][0] + xg0 + u0;
            et[nt][1] = e[nt][1] + xg0 + u1v;
            et[nt][2] = e[nt][2] + xg8 + u0;
            et[nt][3] = e[nt][3] + xg8 + u1v;
        }
    }

    // ---- mix = wc @ energy (2 MMAs); energy B-frags via quad shuffles ----
    float att0[2], att1[2], att2[2], att3[2];
    {
        uint32_t wa0 = *(const uint32_t*)(swch + g * 24 + 2 * tg);
        uint32_t wa1 = *(const uint32_t*)(swch + (g + 8) * 24 + 2 * tg);
        uint32_t wa2 = *(const uint32_t*)(swch + g * 24 + 2 * tg + 8);
        uint32_t wa3 = *(const uint32_t*)(swch + (g + 8) * 24 + 2 * tg + 8);
        const int s1 = 8 * tg + (g >> 1), s2 = s1 + 4;
        const bool podd = g & 1;
        float m[2][4] = {};
        #pragma unroll
        for (int nt = 0; nt < 2; nt++) {
            float f0 = __shfl_sync(FULLMASK, et[nt][0], s1);
            float f1 = __shfl_sync(FULLMASK, et[nt][1], s1);
            float f2 = __shfl_sync(FULLMASK, et[nt][2], s1);
            float f3 = __shfl_sync(FULLMASK, et[nt][3], s1);
            float h0 = __shfl_sync(FULLMASK, et[nt][0], s2);
            float h1 = __shfl_sync(FULLMASK, et[nt][1], s2);
            float h2v = __shfl_sync(FULLMASK, et[nt][2], s2);
            float h3 = __shfl_sync(FULLMASK, et[nt][3], s2);
            uint32_t b0 = h2u(podd ? f1 : f0, podd ? h1 : h0);
            uint32_t b1 = h2u(podd ? f3 : f2, podd ? h3 : h2v);
            mma16(m[nt], wa0, wa1, wa2, wa3, b0, b1);
        }
        // ---- LayerNorm + softmax in regs (quad reductions) ----
        const bool m3 = (tg == 3);   // cols 14,15
        float lg0 = slg[2 * tg], lg1 = slg[2 * tg + 1];
        float lg2 = slg[8 + 2 * tg], lg3 = slg[9 + 2 * tg];
        float lb0 = slb[2 * tg], lb1 = slb[2 * tg + 1];
        float lb2 = slb[8 + 2 * tg], lb3 = slb[9 + 2 * tg];
        #pragma unroll
        for (int rr = 0; rr < 2; rr++) {
            float v0 = m[0][2 * rr], v1 = m[0][2 * rr + 1];
            float v2 = m[1][2 * rr], v3 = m[1][2 * rr + 1];
            float s = v0 + v1 + (m3 ? 0.f : (v2 + v3));
            s += __shfl_xor_sync(FULLMASK, s, 1);
            s += __shfl_xor_sync(FULLMASK, s, 2);
            float mu = s * (1.f / 14.f);
            float d0 = v0 - mu, d1 = v1 - mu, d2 = v2 - mu, d3 = v3 - mu;
            float q = d0 * d0 + d1 * d1 + (m3 ? 0.f : (d2 * d2 + d3 * d3));
            q += __shfl_xor_sync(FULLMASK, q, 1);
            q += __shfl_xor_sync(FULLMASK, q, 2);
            float rsv = rsqrtf(q * (1.f / 14.f) + 1e-5f);
            float t0 = (d0 * rsv * lg0 + lb0) * 0.125f;
            float t1 = (d1 * rsv * lg1 + lb1) * 0.125f;
            float t2 = (d2 * rsv * lg2 + lb2) * 0.125f;
            float t3 = (d3 * rsv * lg3 + lb3) * 0.125f;
            float mx = fmaxf(fmaxf(t0, t1), m3 ? -1e30f : fmaxf(t2, t3));
            mx = fmaxf(mx, __shfl_xor_sync(FULLMASK, mx, 1));
            mx = fmaxf(mx, __shfl_xor_sync(FULLMASK, mx, 2));
            float e0 = __expf(t0 - mx), e1 = __expf(t1 - mx);
            float e2 = m3 ? 0.f : __expf(t2 - mx);
            float e3 = m3 ? 0.f : __expf(t3 - mx);
            float ss = e0 + e1 + e2 + e3;
            ss += __shfl_xor_sync(FULLMASK, ss, 1);
            ss += __shfl_xor_sync(FULLMASK, ss, 2);
            float inv = 1.f / ss;
            att0[rr] = e0 * inv; att1[rr] = e1 * inv;
            att2[rr] = e2 * inv; att3[rr] = e3 * inv;
        }
    }
    // att C-frag -> A-frag: lane-local identity packs
    uint32_t aa0 = h2u(att0[0], att1[0]);
    uint32_t aa1 = h2u(att0[1], att1[1]);
    uint32_t aa2 = h2u(att2[0], att3[0]);
    uint32_t aa3 = h2u(att2[1], att3[1]);

    // ---- vT = Wv-as-A @ x-as-B, fused with out = att @ v  (32 + 8 MMAs) ----
    float* og = out + pair * 896;
    #pragma unroll
    for (int mt = 0; mt < 4; mt++) {
        float dv0[4] = {}, dv1[4] = {};
        #pragma unroll
        for (int k0 = 0; k0 < 4; k0++) {
            const uint2* pw = sPW + (mt * 8 + g) * 36 + 8 * k0 + tg;
            uint2 A01 = pw[0];
            uint2 A23 = pw[4];
            uint32_t b0 = *(const uint32_t*)(sx + g * 72 + k0 * 16 + 2 * tg);
            uint32_t b1 = *(const uint32_t*)(sx + g * 72 + k0 * 16 + 2 * tg + 8);
            mma16(dv0, A01.x, A01.y, A23.x, A23.y, b0, b1);
            uint32_t c0_ = *(const uint32_t*)(sx + (g + 8) * 72 + k0 * 16 + 2 * tg);
            uint32_t c1_ = *(const uint32_t*)(sx + (g + 8) * 72 + k0 * 16 + 2 * tg + 8);
            mma16(dv1, A01.x, A01.y, A23.x, A23.y, c0_, c1_);
        }
        // out columns 16mt..16mt+15: vT C-frags ARE the needed B-frags
        #pragma unroll
        for (int p = 0; p < 2; p++) {
            uint32_t b0 = h2u(dv0[2 * p], dv0[2 * p + 1]);
            uint32_t b1 = h2u(dv1[2 * p], dv1[2 * p + 1]);
            float od[4] = {};
            mma16(od, aa0, aa1, aa2, aa3, b0, b1);
            int cc = (2 * mt + p) * 8 + 2 * tg;
            float2 bb = *(const float2*)(sbv + cc);
            *(float2*)(og + g * 64 + cc) = make_float2(od[0] + bb.x, od[1] + bb.y);
            if (g < 6)
                *(float2*)(og + (g + 8) * 64 + cc) =
                    make_float2(od[2] + bb.x, od[3] + bb.y);
        }
    }
}

// ---------------------------------------------------------------------------
extern "C" void kernel_launch(void* const* d_in, const int* in_sizes, int n_in,
                              void* d_out, int out_size) {
    const float* x   = (const float*)d_in[0];
    const float* wc  = (const float*)d_in[1];
    const float* Wq  = (const float*)d_in[2];
    const float* bq  = (const float*)d_in[3];
    const float* Wk  = (const float*)d_in[4];
    const float* bk  = (const float*)d_in[5];
    const float* Wv  = (const float*)d_in[6];
    const float* bv  = (const float*)d_in[7];
    const float* lng = (const float*)d_in[8];
    const float* lnb = (const float*)d_in[9];
    float* out = (float*)d_out;

    cudaFuncSetAttribute(attn_kernel, cudaFuncAttributeMaxDynamicSharedMemorySize,
                         SMEM_BYTES);

    prep_kernel<<<12, 256>>>(Wq, bq, Wk, bk, Wv, wc);

    // PDL launch: attn may start while prep runs; cudaGridDependencySynchronize()
    // inside attn orders the g_* reads after prep's completion.
    cudaLaunchConfig_t cfg = {};
    cfg.gridDim = dim3(8192, 1, 1);
    cfg.blockDim = dim3(32 * NW, 1, 1);
    cfg.dynamicSmemBytes = SMEM_BYTES;
    cfg.stream = 0;
    cudaLaunchAttribute attrs[1];
    attrs[0].id = cudaLaunchAttributeProgrammaticStreamSerialization;
    attrs[0].val.programmaticStreamSerializationAllowed = 1;
    cfg.attrs = attrs;
    cfg.numAttrs = 1;
    cudaLaunchKernelEx(&cfg, attn_kernel, x, bv, lng, lnb, out);
}

// round 16
// speedup vs baseline: 1.0908x; 1.0908x over previous
#include <cuda_runtime.h>
#include <cuda_fp16.h>
#include <cstdint>

// ---------------------------------------------------------------------------
// ChannelMultiHeadAttention, fp32 in/out, fp16 tensor-core compute (m16n8k16).
//   energy = x A x^T + xu1 1^T + 1 xu2^T + c0,  A = Wq^T Wk
//   out    = att @ v + bv,  v = x @ Wv^T   (computed as vT C-frags)
// R16: attn kernel byte-identical to R9/R14 (best measured). Prep = ONE fused
//      kernel (direct PA packing, no g_Af intermediate, float4 staging loads).
//      No PDL (R15 showed it costs ~7us inside attn).
// ---------------------------------------------------------------------------

#define FULLMASK 0xffffffffu

// Packed B-frags of [A | u1 u2 | 0pad]: entry[(k0*4+tq)*84 + e] =
//   {h2(A[16k0+2tq][e], A[16k0+2tq+1][e]), h2(A[16k0+2tq+8][e], A[16k0+2tq+9][e])}
__device__ uint2  g_PA[16 * 84];
// Packed A-frags of Wv: entry[(mt*8+q)*36 + cp] =
//   {h2(Wv[16mt+q][2cp], [2cp+1]), h2(Wv[16mt+q+8][2cp], [2cp+1])}
__device__ uint2  g_PW[32 * 36];
__device__ __half g_wch[256];     // wc padded 16x16 fp16
__device__ float  g_c0[1];

__device__ __forceinline__ uint32_t h2u(float a, float b) {
    __half2 h = __floats2half2_rn(a, b);
    return *(uint32_t*)&h;
}

__device__ __forceinline__ void mma16(float* d, uint32_t a0, uint32_t a1, uint32_t a2,
                                      uint32_t a3, uint32_t b0, uint32_t b1) {
    asm("mma.sync.aligned.m16n8k16.row.col.f32.f16.f16.f32 "
        "{%0,%1,%2,%3}, {%4,%5,%6,%7}, {%8,%9}, {%0,%1,%2,%3};"
        : "+f"(d[0]), "+f"(d[1]), "+f"(d[2]), "+f"(d[3])
        : "r"(a0), "r"(a1), "r"(a2), "r"(a3), "r"(b0), "r"(b1));
}

// ---------------------------------------------------------------------------
// Fused prep: blocks 0-7 pack P_A directly (4 smem dot-products per entry,
// no g_Af intermediate); blocks 8-11 pack P_W + wch + c0 (no A dependency).
// Staging loads are float4 to minimize exposed cold-DRAM latency.
// ---------------------------------------------------------------------------
__global__ void prep_kernel(const float* __restrict__ Wq, const float* __restrict__ bq,
                            const float* __restrict__ Wk, const float* __restrict__ bk,
                            const float* __restrict__ Wv, const float* __restrict__ wc) {
    int t = threadIdx.x, b = blockIdx.x;
    if (b < 8) {
        __shared__ float sWq[4096], sWk[4096];
        {   // float4 staging: 1024 float4 per matrix, 256 threads -> 4 rounds
            const float4* q4 = (const float4*)Wq;
            const float4* k4 = (const float4*)Wk;
            #pragma unroll
            for (int i = 0; i < 4; i++) {
                ((float4*)sWq)[t + 256 * i] = q4[t + 256 * i];
                ((float4*)sWk)[t + 256 * i] = k4[t + 256 * i];
            }
        }
        __syncthreads();

        int idx = b * 144 + t;              // 1152 PA entries, 144 per block
        if (t < 144) {
            int kq = idx / 72, e = idx % 72;
            int k0 = kq >> 2, tq = kq & 3;
            int db = 16 * k0 + 2 * tq;      // rows db, db+1, db+8, db+9 (even)
            float a0 = 0.f, a1 = 0.f, a2 = 0.f, a3 = 0.f;
            if (e < 64) {
                #pragma unroll 4
                for (int f = 0; f < 64; f++) {
                    float wk = sWk[f * 64 + e];
                    float2 q01 = *(const float2*)(sWq + f * 64 + db);
                    float2 q89 = *(const float2*)(sWq + f * 64 + db + 8);
                    a0 += q01.x * wk; a1 += q01.y * wk;
                    a2 += q89.x * wk; a3 += q89.y * wk;
                }
            } else if (e == 64) {           // u1 = Wq^T bk
                #pragma unroll 4
                for (int f = 0; f < 64; f++) {
                    float bkf = bk[f];
                    float2 q01 = *(const float2*)(sWq + f * 64 + db);
                    float2 q89 = *(const float2*)(sWq + f * 64 + db + 8);
                    a0 += q01.x * bkf; a1 += q01.y * bkf;
                    a2 += q89.x * bkf; a3 += q89.y * bkf;
                }
            } else if (e == 65) {           // u2 = Wk^T bq
                #pragma unroll 4
                for (int f = 0; f < 64; f++) {
                    float bqf = bq[f];
                    float2 k01 = *(const float2*)(sWk + f * 64 + db);
                    float2 k89 = *(const float2*)(sWk + f * 64 + db + 8);
                    a0 += k01.x * bqf; a1 += k01.y * bqf;
                    a2 += k89.x * bqf; a3 += k89.y * bqf;
                }
            }
            g_PA[kq * 84 + e] = make_uint2(h2u(a0, a1), h2u(a2, a3));
        }
    } else {
        // pack P_W (A-operand of vT GEMM = Wv row-major), 1152 entries
        for (int idx = (b - 8) * 256 + t; idx < 32 * 36; idx += 1024) {
            int r = idx / 36, cp = idx % 36;
            int mt = r >> 3, q = r & 7;
            uint2 u = make_uint2(0u, 0u);
            if (cp < 32) {
                int e0 = 16 * mt + q;
                u.x = h2u(Wv[e0 * 64 + 2 * cp], Wv[e0 * 64 + 2 * cp + 1]);
                u.y = h2u(Wv[(e0 + 8) * 64 + 2 * cp], Wv[(e0 + 8) * 64 + 2 * cp + 1]);
            }
            g_PW[idx] = u;
        }
        if (b == 8) {
            int a0 = t >> 4, c = t & 15;
            float v = (a0 < 14 && c < 14) ? wc[a0 * 14 + c] : 0.f;
            g_wch[t] = __float2half_rn(v);
            if (t == 0) {
                float cc = 0.f;
                for (int f = 0; f < 64; f++) cc += bq[f] * bk[f];
                g_c0[0] = cc;
            }
        }
    }
}

// ---------------------------------------------------------------------------
// Main: 1 warp = 1 pair, 8 warps/CTA, 8192 CTAs (exact). Byte-identical R9.
// smem: PA 10752 + PW 9216 + wc 768 + bv 256 + ln 128 + 8 x 2432 = 40576 B
// ---------------------------------------------------------------------------
static const int NW = 8;
static const int SMEM_BYTES = 10752 + 9216 + 768 + 256 + 128 + NW * 2432;  // 40576

__global__ __launch_bounds__(32 * NW, 3)
void attn_kernel(const float* __restrict__ x, const float* __restrict__ bv,
                 const float* __restrict__ lng, const float* __restrict__ lnb,
                 float* __restrict__ out) {
    extern __shared__ __align__(16) unsigned char smraw[];
    uint2*  sPA  = (uint2*)smraw;                    // 16*84
    uint2*  sPW  = sPA + 16 * 84;                    // 32*36
    __half* swch = (__half*)(sPW + 32 * 36);         // 16 x 24
    float*  sbv  = (float*)(swch + 384);             // 64
    float*  slg  = sbv + 64;                         // 16
    float*  slb  = slg + 16;                         // 16
    __half* stil = (__half*)(slb + 16);              // NW x 1216 halves

    const int t = threadIdx.x, w = t >> 5, l = t & 31;
    const int g = l >> 2, tg = l & 3;

    for (int i = t; i < 16 * 84; i += 32 * NW) sPA[i] = g_PA[i];
    for (int i = t; i < 32 * 36; i += 32 * NW) sPW[i] = g_PW[i];
    if (t < 256) swch[(t >> 4) * 24 + (t & 15)] = g_wch[t];
    if (t < 64) sbv[t] = bv[t];
    if (t < 16) {
        slg[t] = (t < 14) ? lng[t] : 0.f;
        slb[t] = (t < 14) ? lnb[t] : 0.f;
    }
    __syncthreads();

    const size_t pair = (size_t)blockIdx.x * NW + w;
    const float c0v = g_c0[0];

    __half* sx   = stil + w * 1216;          // 16 rows x 72 halves
    float*  sxu1 = (float*)(sx + 1152);      // 16
    float*  sxu2 = sxu1 + 16;                // 16

    // ---- load x tile -> fp16 smem; zero rows 14,15 ----
    const float4* xg4 = (const float4*)(x + pair * 896);
    #pragma unroll
    for (int it = 0; it < 7; it++) {
        int k = l + 32 * it;
        float4 v = xg4[k];
        int row = k >> 4, c4 = k & 15;
        *(uint2*)(sx + row * 72 + c4 * 4) = make_uint2(h2u(v.x, v.y), h2u(v.z, v.w));
    }
    for (int i = l; i < 72; i += 32) ((uint32_t*)(sx + 14 * 72))[i] = 0u;
    __syncwarp();

    // ---- Y = x @ [A | u1 u2]  (4 k0 x 9 n0 = 36 MMAs) ----
    float dY[9][4] = {};
    #pragma unroll
    for (int k0 = 0; k0 < 4; k0++) {
        uint32_t a0 = *(const uint32_t*)(sx + g * 72 + k0 * 16 + 2 * tg);
        uint32_t a1 = *(const uint32_t*)(sx + (g + 8) * 72 + k0 * 16 + 2 * tg);
        uint32_t a2 = *(const uint32_t*)(sx + g * 72 + k0 * 16 + 2 * tg + 8);
        uint32_t a3 = *(const uint32_t*)(sx + (g + 8) * 72 + k0 * 16 + 2 * tg + 8);
        const uint2* pa = sPA + (k0 * 4 + tg) * 84 + g;
        #pragma unroll
        for (int n0 = 0; n0 < 9; n0++) {
            uint2 b = pa[n0 * 8];
            mma16(dY[n0], a0, a1, a2, a3, b.x, b.y);
        }
    }
    // dY[8] cols 64-71: tg==0 lanes hold (xu1, xu2) for rows g, g+8
    if (tg == 0) {
        sxu1[g] = dY[8][0]; sxu2[g] = dY[8][1];
        sxu1[g + 8] = dY[8][2]; sxu2[g + 8] = dY[8][3];
    }

    // ---- energy = y @ x^T  (8 MMAs); y A-frags are lane-local packs ----
    float e[2][4] = {};
    #pragma unroll
    for (int k0 = 0; k0 < 4; k0++) {
        uint32_t a0 = h2u(dY[2 * k0][0], dY[2 * k0][1]);
        uint32_t a1 = h2u(dY[2 * k0][2], dY[2 * k0][3]);
        uint32_t a2 = h2u(dY[2 * k0 + 1][0], dY[2 * k0 + 1][1]);
        uint32_t a3 = h2u(dY[2 * k0 + 1][2], dY[2 * k0 + 1][3]);
        #pragma unroll
        for (int nt = 0; nt < 2; nt++) {
            uint32_t b0 = *(const uint32_t*)(sx + (nt * 8 + g) * 72 + k0 * 16 + 2 * tg);
            uint32_t b1 = *(const uint32_t*)(sx + (nt * 8 + g) * 72 + k0 * 16 + 2 * tg + 8);
            mma16(e[nt], a0, a1, a2, a3, b0, b1);
        }
    }
    __syncwarp();   // sxu stores visible
    float et[2][4];
    {
        float xg0 = sxu1[g] + c0v, xg8 = sxu1[g + 8] + c0v;
        #pragma unroll
        for (int nt = 0; nt < 2; nt++) {
            int j0 = nt * 8 + 2 * tg;
            float u0 = sxu2[j0], u1v = sxu2[j0 + 1];
            et[nt][0] = e[nt][0] + xg0 + u0;
            et[nt][1] = e[nt][1] + xg0 + u1v;
            et[nt][2] = e[nt][2] + xg8 + u0;
            et[nt][3] = e[nt][3] + xg8 + u1v;
        }
    }

    // ---- mix = wc @ energy (2 MMAs); energy B-frags via quad shuffles ----
    float att0[2], att1[2], att2[2], att3[2];
    {
        uint32_t wa0 = *(const uint32_t*)(swch + g * 24 + 2 * tg);
        uint32_t wa1 = *(const uint32_t*)(swch + (g + 8) * 24 + 2 * tg);
        uint32_t wa2 = *(const uint32_t*)(swch + g * 24 + 2 * tg + 8);
        uint32_t wa3 = *(const uint32_t*)(swch + (g + 8) * 24 + 2 * tg + 8);
        const int s1 = 8 * tg + (g >> 1), s2 = s1 + 4;
        const bool podd = g & 1;
        float m[2][4] = {};
        #pragma unroll
        for (int nt = 0; nt < 2; nt++) {
            float f0 = __shfl_sync(FULLMASK, et[nt][0], s1);
            float f1 = __shfl_sync(FULLMASK, et[nt][1], s1);
            float f2 = __shfl_sync(FULLMASK, et[nt][2], s1);
            float f3 = __shfl_sync(FULLMASK, et[nt][3], s1);
            float h0 = __shfl_sync(FULLMASK, et[nt][0], s2);
            float h1 = __shfl_sync(FULLMASK, et[nt][1], s2);
            float h2v = __shfl_sync(FULLMASK, et[nt][2], s2);
            float h3 = __shfl_sync(FULLMASK, et[nt][3], s2);
            uint32_t b0 = h2u(podd ? f1 : f0, podd ? h1 : h0);
            uint32_t b1 = h2u(podd ? f3 : f2, podd ? h3 : h2v);
            mma16(m[nt], wa0, wa1, wa2, wa3, b0, b1);
        }
        // ---- LayerNorm + softmax in regs (quad reductions) ----
        const bool m3 = (tg == 3);   // cols 14,15
        float lg0 = slg[2 * tg], lg1 = slg[2 * tg + 1];
        float lg2 = slg[8 + 2 * tg], lg3 = slg[9 + 2 * tg];
        float lb0 = slb[2 * tg], lb1 = slb[2 * tg + 1];
        float lb2 = slb[8 + 2 * tg], lb3 = slb[9 + 2 * tg];
        #pragma unroll
        for (int rr = 0; rr < 2; rr++) {
            float v0 = m[0][2 * rr], v1 = m[0][2 * rr + 1];
            float v2 = m[1][2 * rr], v3 = m[1][2 * rr + 1];
            float s = v0 + v1 + (m3 ? 0.f : (v2 + v3));
            s += __shfl_xor_sync(FULLMASK, s, 1);
            s += __shfl_xor_sync(FULLMASK, s, 2);
            float mu = s * (1.f / 14.f);
            float d0 = v0 - mu, d1 = v1 - mu, d2 = v2 - mu, d3 = v3 - mu;
            float q = d0 * d0 + d1 * d1 + (m3 ? 0.f : (d2 * d2 + d3 * d3));
            q += __shfl_xor_sync(FULLMASK, q, 1);
            q += __shfl_xor_sync(FULLMASK, q, 2);
            float rsv = rsqrtf(q * (1.f / 14.f) + 1e-5f);
            float t0 = (d0 * rsv * lg0 + lb0) * 0.125f;
            float t1 = (d1 * rsv * lg1 + lb1) * 0.125f;
            float t2 = (d2 * rsv * lg2 + lb2) * 0.125f;
            float t3 = (d3 * rsv * lg3 + lb3) * 0.125f;
            float mx = fmaxf(fmaxf(t0, t1), m3 ? -1e30f : fmaxf(t2, t3));
            mx = fmaxf(mx, __shfl_xor_sync(FULLMASK, mx, 1));
            mx = fmaxf(mx, __shfl_xor_sync(FULLMASK, mx, 2));
            float e0 = __expf(t0 - mx), e1 = __expf(t1 - mx);
            float e2 = m3 ? 0.f : __expf(t2 - mx);
            float e3 = m3 ? 0.f : __expf(t3 - mx);
            float ss = e0 + e1 + e2 + e3;
            ss += __shfl_xor_sync(FULLMASK, ss, 1);
            ss += __shfl_xor_sync(FULLMASK, ss, 2);
            float inv = 1.f / ss;
            att0[rr] = e0 * inv; att1[rr] = e1 * inv;
            att2[rr] = e2 * inv; att3[rr] = e3 * inv;
        }
    }
    // att C-frag -> A-frag: lane-local identity packs
    uint32_t aa0 = h2u(att0[0], att1[0]);
    uint32_t aa1 = h2u(att0[1], att1[1]);
    uint32_t aa2 = h2u(att2[0], att3[0]);
    uint32_t aa3 = h2u(att2[1], att3[1]);

    // ---- vT = Wv-as-A @ x-as-B, fused with out = att @ v  (32 + 8 MMAs) ----
    float* og = out + pair * 896;
    #pragma unroll
    for (int mt = 0; mt < 4; mt++) {
        float dv0[4] = {}, dv1[4] = {};
        #pragma unroll
        for (int k0 = 0; k0 < 4; k0++) {
            const uint2* pw = sPW + (mt * 8 + g) * 36 + 8 * k0 + tg;
            uint2 A01 = pw[0];
            uint2 A23 = pw[4];
            uint32_t b0 = *(const uint32_t*)(sx + g * 72 + k0 * 16 + 2 * tg);
            uint32_t b1 = *(const uint32_t*)(sx + g * 72 + k0 * 16 + 2 * tg + 8);
            mma16(dv0, A01.x, A01.y, A23.x, A23.y, b0, b1);
            uint32_t c0_ = *(const uint32_t*)(sx + (g + 8) * 72 + k0 * 16 + 2 * tg);
            uint32_t c1_ = *(const uint32_t*)(sx + (g + 8) * 72 + k0 * 16 + 2 * tg + 8);
            mma16(dv1, A01.x, A01.y, A23.x, A23.y, c0_, c1_);
        }
        // out columns 16mt..16mt+15: vT C-frags ARE the needed B-frags
        #pragma unroll
        for (int p = 0; p < 2; p++) {
            uint32_t b0 = h2u(dv0[2 * p], dv0[2 * p + 1]);
            uint32_t b1 = h2u(dv1[2 * p], dv1[2 * p + 1]);
            float od[4] = {};
            mma16(od, aa0, aa1, aa2, aa3, b0, b1);
            int cc = (2 * mt + p) * 8 + 2 * tg;
            float2 bb = *(const float2*)(sbv + cc);
            *(float2*)(og + g * 64 + cc) = make_float2(od[0] + bb.x, od[1] + bb.y);
            if (g < 6)
                *(float2*)(og + (g + 8) * 64 + cc) =
                    make_float2(od[2] + bb.x, od[3] + bb.y);
        }
    }
}

// ---------------------------------------------------------------------------
extern "C" void kernel_launch(void* const* d_in, const int* in_sizes, int n_in,
                              void* d_out, int out_size) {
    const float* x   = (const float*)d_in[0];
    const float* wc  = (const float*)d_in[1];
    const float* Wq  = (const float*)d_in[2];
    const float* bq  = (const float*)d_in[3];
    const float* Wk  = (const float*)d_in[4];
    const float* bk  = (const float*)d_in[5];
    const float* Wv  = (const float*)d_in[6];
    const float* bv  = (const float*)d_in[7];
    const float* lng = (const float*)d_in[8];
    const float* lnb = (const float*)d_in[9];
    float* out = (float*)d_out;

    cudaFuncSetAttribute(attn_kernel, cudaFuncAttributeMaxDynamicSharedMemorySize,
                         SMEM_BYTES);

    prep_kernel<<<12, 256>>>(Wq, bq, Wk, bk, Wv, wc);
    attn_kernel<<<8192, 32 * NW, SMEM_BYTES>>>(x, bv, lng, lnb, out);
}

// round 17
// speedup vs baseline: 1.0925x; 1.0016x over previous
#include <cuda_runtime.h>
#include <cuda_fp16.h>
#include <cstdint>

// ---------------------------------------------------------------------------
// ChannelMultiHeadAttention, fp32 in/out, fp16 tensor-core compute (m16n8k16).
//   energy = x A x^T + xu1 1^T + 1 xu2^T + c0,  A = Wq^T Wk
//   out    = att @ v + bv,  v = x @ Wv^T   (computed as vT C-frags)
// R17: R16 + ONE isolated change: vT loop reads x frag words from a flat
//      16-entry register array (loaded once after dY dies) instead of
//      re-reading the same smem words 4x (once per mt). Loop structure,
//      accumulators, and everything else byte-identical to R16/R9.
// ---------------------------------------------------------------------------

#define FULLMASK 0xffffffffu

// Packed B-frags of [A | u1 u2 | 0pad]: entry[(k0*4+tq)*84 + e] =
//   {h2(A[16k0+2tq][e], A[16k0+2tq+1][e]), h2(A[16k0+2tq+8][e], A[16k0+2tq+9][e])}
__device__ uint2  g_PA[16 * 84];
// Packed A-frags of Wv: entry[(mt*8+q)*36 + cp] =
//   {h2(Wv[16mt+q][2cp], [2cp+1]), h2(Wv[16mt+q+8][2cp], [2cp+1])}
__device__ uint2  g_PW[32 * 36];
__device__ __half g_wch[256];     // wc padded 16x16 fp16
__device__ float  g_c0[1];

__device__ __forceinline__ uint32_t h2u(float a, float b) {
    __half2 h = __floats2half2_rn(a, b);
    return *(uint32_t*)&h;
}

__device__ __forceinline__ void mma16(float* d, uint32_t a0, uint32_t a1, uint32_t a2,
                                      uint32_t a3, uint32_t b0, uint32_t b1) {
    asm("mma.sync.aligned.m16n8k16.row.col.f32.f16.f16.f32 "
        "{%0,%1,%2,%3}, {%4,%5,%6,%7}, {%8,%9}, {%0,%1,%2,%3};"
        : "+f"(d[0]), "+f"(d[1]), "+f"(d[2]), "+f"(d[3])
        : "r"(a0), "r"(a1), "r"(a2), "r"(a3), "r"(b0), "r"(b1));
}

// ---------------------------------------------------------------------------
// Fused prep: blocks 0-7 pack P_A directly (4 smem dot-products per entry,
// no g_Af intermediate); blocks 8-11 pack P_W + wch + c0 (no A dependency).
// ---------------------------------------------------------------------------
__global__ void prep_kernel(const float* __restrict__ Wq, const float* __restrict__ bq,
                            const float* __restrict__ Wk, const float* __restrict__ bk,
                            const float* __restrict__ Wv, const float* __restrict__ wc) {
    int t = threadIdx.x, b = blockIdx.x;
    if (b < 8) {
        __shared__ float sWq[4096], sWk[4096];
        {   // float4 staging: 1024 float4 per matrix, 256 threads -> 4 rounds
            const float4* q4 = (const float4*)Wq;
            const float4* k4 = (const float4*)Wk;
            #pragma unroll
            for (int i = 0; i < 4; i++) {
                ((float4*)sWq)[t + 256 * i] = q4[t + 256 * i];
                ((float4*)sWk)[t + 256 * i] = k4[t + 256 * i];
            }
        }
        __syncthreads();

        int idx = b * 144 + t;              // 1152 PA entries, 144 per block
        if (t < 144) {
            int kq = idx / 72, e = idx % 72;
            int k0 = kq >> 2, tq = kq & 3;
            int db = 16 * k0 + 2 * tq;      // rows db, db+1, db+8, db+9 (even)
            float a0 = 0.f, a1 = 0.f, a2 = 0.f, a3 = 0.f;
            if (e < 64) {
                #pragma unroll 4
                for (int f = 0; f < 64; f++) {
                    float wk = sWk[f * 64 + e];
                    float2 q01 = *(const float2*)(sWq + f * 64 + db);
                    float2 q89 = *(const float2*)(sWq + f * 64 + db + 8);
                    a0 += q01.x * wk; a1 += q01.y * wk;
                    a2 += q89.x * wk; a3 += q89.y * wk;
                }
            } else if (e == 64) {           // u1 = Wq^T bk
                #pragma unroll 4
                for (int f = 0; f < 64; f++) {
                    float bkf = bk[f];
                    float2 q01 = *(const float2*)(sWq + f * 64 + db);
                    float2 q89 = *(const float2*)(sWq + f * 64 + db + 8);
                    a0 += q01.x * bkf; a1 += q01.y * bkf;
                    a2 += q89.x * bkf; a3 += q89.y * bkf;
                }
            } else if (e == 65) {           // u2 = Wk^T bq
                #pragma unroll 4
                for (int f = 0; f < 64; f++) {
                    float bqf = bq[f];
                    float2 k01 = *(const float2*)(sWk + f * 64 + db);
                    float2 k89 = *(const float2*)(sWk + f * 64 + db + 8);
                    a0 += k01.x * bqf; a1 += k01.y * bqf;
                    a2 += k89.x * bqf; a3 += k89.y * bqf;
                }
            }
            g_PA[kq * 84 + e] = make_uint2(h2u(a0, a1), h2u(a2, a3));
        }
    } else {
        // pack P_W (A-operand of vT GEMM = Wv row-major), 1152 entries
        for (int idx = (b - 8) * 256 + t; idx < 32 * 36; idx += 1024) {
            int r = idx / 36, cp = idx % 36;
            int mt = r >> 3, q = r & 7;
            uint2 u = make_uint2(0u, 0u);
            if (cp < 32) {
                int e0 = 16 * mt + q;
                u.x = h2u(Wv[e0 * 64 + 2 * cp], Wv[e0 * 64 + 2 * cp + 1]);
                u.y = h2u(Wv[(e0 + 8) * 64 + 2 * cp], Wv[(e0 + 8) * 64 + 2 * cp + 1]);
            }
            g_PW[idx] = u;
        }
        if (b == 8) {
            int a0 = t >> 4, c = t & 15;
            float v = (a0 < 14 && c < 14) ? wc[a0 * 14 + c] : 0.f;
            g_wch[t] = __float2half_rn(v);
            if (t == 0) {
                float cc = 0.f;
                for (int f = 0; f < 64; f++) cc += bq[f] * bk[f];
                g_c0[0] = cc;
            }
        }
    }
}

// ---------------------------------------------------------------------------
// Main: 1 warp = 1 pair, 8 warps/CTA, 8192 CTAs (exact).
// smem: PA 10752 + PW 9216 + wc 768 + bv 256 + ln 128 + 8 x 2432 = 40576 B
// ---------------------------------------------------------------------------
static const int NW = 8;
static const int SMEM_BYTES = 10752 + 9216 + 768 + 256 + 128 + NW * 2432;  // 40576

__global__ __launch_bounds__(32 * NW, 3)
void attn_kernel(const float* __restrict__ x, const float* __restrict__ bv,
                 const float* __restrict__ lng, const float* __restrict__ lnb,
                 float* __restrict__ out) {
    extern __shared__ __align__(16) unsigned char smraw[];
    uint2*  sPA  = (uint2*)smraw;                    // 16*84
    uint2*  sPW  = sPA + 16 * 84;                    // 32*36
    __half* swch = (__half*)(sPW + 32 * 36);         // 16 x 24
    float*  sbv  = (float*)(swch + 384);             // 64
    float*  slg  = sbv + 64;                         // 16
    float*  slb  = slg + 16;                         // 16
    __half* stil = (__half*)(slb + 16);              // NW x 1216 halves

    const int t = threadIdx.x, w = t >> 5, l = t & 31;
    const int g = l >> 2, tg = l & 3;

    for (int i = t; i < 16 * 84; i += 32 * NW) sPA[i] = g_PA[i];
    for (int i = t; i < 32 * 36; i += 32 * NW) sPW[i] = g_PW[i];
    if (t < 256) swch[(t >> 4) * 24 + (t & 15)] = g_wch[t];
    if (t < 64) sbv[t] = bv[t];
    if (t < 16) {
        slg[t] = (t < 14) ? lng[t] : 0.f;
        slb[t] = (t < 14) ? lnb[t] : 0.f;
    }
    __syncthreads();

    const size_t pair = (size_t)blockIdx.x * NW + w;
    const float c0v = g_c0[0];

    __half* sx   = stil + w * 1216;          // 16 rows x 72 halves
    float*  sxu1 = (float*)(sx + 1152);      // 16
    float*  sxu2 = sxu1 + 16;                // 16

    // ---- load x tile -> fp16 smem; zero rows 14,15 ----
    const float4* xg4 = (const float4*)(x + pair * 896);
    #pragma unroll
    for (int it = 0; it < 7; it++) {
        int k = l + 32 * it;
        float4 v = xg4[k];
        int row = k >> 4, c4 = k & 15;
        *(uint2*)(sx + row * 72 + c4 * 4) = make_uint2(h2u(v.x, v.y), h2u(v.z, v.w));
    }
    for (int i = l; i < 72; i += 32) ((uint32_t*)(sx + 14 * 72))[i] = 0u;
    __syncwarp();

    // ---- Y = x @ [A | u1 u2]  (4 k0 x 9 n0 = 36 MMAs) ----
    float dY[9][4] = {};
    #pragma unroll
    for (int k0 = 0; k0 < 4; k0++) {
        uint32_t a0 = *(const uint32_t*)(sx + g * 72 + k0 * 16 + 2 * tg);
        uint32_t a1 = *(const uint32_t*)(sx + (g + 8) * 72 + k0 * 16 + 2 * tg);
        uint32_t a2 = *(const uint32_t*)(sx + g * 72 + k0 * 16 + 2 * tg + 8);
        uint32_t a3 = *(const uint32_t*)(sx + (g + 8) * 72 + k0 * 16 + 2 * tg + 8);
        const uint2* pa = sPA + (k0 * 4 + tg) * 84 + g;
        #pragma unroll
        for (int n0 = 0; n0 < 9; n0++) {
            uint2 b = pa[n0 * 8];
            mma16(dY[n0], a0, a1, a2, a3, b.x, b.y);
        }
    }
    // dY[8] cols 64-71: tg==0 lanes hold (xu1, xu2) for rows g, g+8
    if (tg == 0) {
        sxu1[g] = dY[8][0]; sxu2[g] = dY[8][1];
        sxu1[g + 8] = dY[8][2]; sxu2[g + 8] = dY[8][3];
    }

    // ---- energy = y @ x^T  (8 MMAs); y A-frags are lane-local packs ----
    float e[2][4] = {};
    #pragma unroll
    for (int k0 = 0; k0 < 4; k0++) {
        uint32_t a0 = h2u(dY[2 * k0][0], dY[2 * k0][1]);
        uint32_t a1 = h2u(dY[2 * k0][2], dY[2 * k0][3]);
        uint32_t a2 = h2u(dY[2 * k0 + 1][0], dY[2 * k0 + 1][1]);
        uint32_t a3 = h2u(dY[2 * k0 + 1][2], dY[2 * k0 + 1][3]);
        #pragma unroll
        for (int nt = 0; nt < 2; nt++) {
            uint32_t b0 = *(const uint32_t*)(sx + (nt * 8 + g) * 72 + k0 * 16 + 2 * tg);
            uint32_t b1 = *(const uint32_t*)(sx + (nt * 8 + g) * 72 + k0 * 16 + 2 * tg + 8);
            mma16(e[nt], a0, a1, a2, a3, b0, b1);
        }
    }
    __syncwarp();   // sxu stores visible
    float et[2][4];
    {
        float xg0 = sxu1[g] + c0v, xg8 = sxu1[g + 8] + c0v;
        #pragma unroll
        for (int nt = 0; nt < 2; nt++) {
            int j0 = nt * 8 + 2 * tg;
            float u0 = sxu2[j0], u1v = sxu2[j0 + 1];
            et[nt][0] = e[nt][0] + xg0 + u0;
            et[nt][1] = e[nt][1] + xg0 + u1v;
            et[nt][2] = e[nt][2] + xg8 + u0;
            et[nt][3] = e[nt][3] + xg8 + u1v;
        }
    }

    // ---- mix = wc @ energy (2 MMAs); energy B-frags via quad shuffles ----
    float att0[2], att1[2], att2[2], att3[2];
    {
        uint32_t wa0 = *(const uint32_t*)(swch + g * 24 + 2 * tg);
        uint32_t wa1 = *(const uint32_t*)(swch + (g + 8) * 24 + 2 * tg);
        uint32_t wa2 = *(const uint32_t*)(swch + g * 24 + 2 * tg + 8);
        uint32_t wa3 = *(const uint32_t*)(swch + (g + 8) * 24 + 2 * tg + 8);
        const int s1 = 8 * tg + (g >> 1), s2 = s1 + 4;
        const bool podd = g & 1;
        float m[2][4] = {};
        #pragma unroll
        for (int nt = 0; nt < 2; nt++) {
            float f0 = __shfl_sync(FULLMASK, et[nt][0], s1);
            float f1 = __shfl_sync(FULLMASK, et[nt][1], s1);
            float f2 = __shfl_sync(FULLMASK, et[nt][2], s1);
            float f3 = __shfl_sync(FULLMASK, et[nt][3], s1);
            float h0 = __shfl_sync(FULLMASK, et[nt][0], s2);
            float h1 = __shfl_sync(FULLMASK, et[nt][1], s2);
            float h2v = __shfl_sync(FULLMASK, et[nt][2], s2);
            float h3 = __shfl_sync(FULLMASK, et[nt][3], s2);
            uint32_t b0 = h2u(podd ? f1 : f0, podd ? h1 : h0);
            uint32_t b1 = h2u(podd ? f3 : f2, podd ? h3 : h2v);
            mma16(m[nt], wa0, wa1, wa2, wa3, b0, b1);
        }
        // ---- LayerNorm + softmax in regs (quad reductions) ----
        const bool m3 = (tg == 3);   // cols 14,15
        float lg0 = slg[2 * tg], lg1 = slg[2 * tg + 1];
        float lg2 = slg[8 + 2 * tg], lg3 = slg[9 + 2 * tg];
        float lb0 = slb[2 * tg], lb1 = slb[2 * tg + 1];
        float lb2 = slb[8 + 2 * tg], lb3 = slb[9 + 2 * tg];
        #pragma unroll
        for (int rr = 0; rr < 2; rr++) {
            float v0 = m[0][2 * rr], v1 = m[0][2 * rr + 1];
            float v2 = m[1][2 * rr], v3 = m[1][2 * rr + 1];
            float s = v0 + v1 + (m3 ? 0.f : (v2 + v3));
            s += __shfl_xor_sync(FULLMASK, s, 1);
            s += __shfl_xor_sync(FULLMASK, s, 2);
            float mu = s * (1.f / 14.f);
            float d0 = v0 - mu, d1 = v1 - mu, d2 = v2 - mu, d3 = v3 - mu;
            float q = d0 * d0 + d1 * d1 + (m3 ? 0.f : (d2 * d2 + d3 * d3));
            q += __shfl_xor_sync(FULLMASK, q, 1);
            q += __shfl_xor_sync(FULLMASK, q, 2);
            float rsv = rsqrtf(q * (1.f / 14.f) + 1e-5f);
            float t0 = (d0 * rsv * lg0 + lb0) * 0.125f;
            float t1 = (d1 * rsv * lg1 + lb1) * 0.125f;
            float t2 = (d2 * rsv * lg2 + lb2) * 0.125f;
            float t3 = (d3 * rsv * lg3 + lb3) * 0.125f;
            float mx = fmaxf(fmaxf(t0, t1), m3 ? -1e30f : fmaxf(t2, t3));
            mx = fmaxf(mx, __shfl_xor_sync(FULLMASK, mx, 1));
            mx = fmaxf(mx, __shfl_xor_sync(FULLMASK, mx, 2));
            float e0 = __expf(t0 - mx), e1 = __expf(t1 - mx);
            float e2 = m3 ? 0.f : __expf(t2 - mx);
            float e3 = m3 ? 0.f : __expf(t3 - mx);
            float ss = e0 + e1 + e2 + e3;
            ss += __shfl_xor_sync(FULLMASK, ss, 1);
            ss += __shfl_xor_sync(FULLMASK, ss, 2);
            float inv = 1.f / ss;
            att0[rr] = e0 * inv; att1[rr] = e1 * inv;
            att2[rr] = e2 * inv; att3[rr] = e3 * inv;
        }
    }
    // att C-frag -> A-frag: lane-local identity packs
    uint32_t aa0 = h2u(att0[0], att1[0]);
    uint32_t aa1 = h2u(att0[1], att1[1]);
    uint32_t aa2 = h2u(att2[0], att3[0]);
    uint32_t aa3 = h2u(att2[1], att3[1]);

    // ---- hoist x frag words ONCE (dY registers are dead here) ----
    // xB[4*k0+0]=row g cols 16k0+2tg,+1 ; +1=row g+8 same ; +2/+3 = cols +8
    uint32_t xB[16];
    #pragma unroll
    for (int k0 = 0; k0 < 4; k0++) {
        xB[4 * k0 + 0] = *(const uint32_t*)(sx + g * 72 + k0 * 16 + 2 * tg);
        xB[4 * k0 + 1] = *(const uint32_t*)(sx + (g + 8) * 72 + k0 * 16 + 2 * tg);
        xB[4 * k0 + 2] = *(const uint32_t*)(sx + g * 72 + k0 * 16 + 2 * tg + 8);
        xB[4 * k0 + 3] = *(const uint32_t*)(sx + (g + 8) * 72 + k0 * 16 + 2 * tg + 8);
    }

    // ---- vT = Wv-as-A @ x-as-B, fused with out = att @ v  (32 + 8 MMAs) ----
    float* og = out + pair * 896;
    #pragma unroll
    for (int mt = 0; mt < 4; mt++) {
        float dv0[4] = {}, dv1[4] = {};
        #pragma unroll
        for (int k0 = 0; k0 < 4; k0++) {
            const uint2* pw = sPW + (mt * 8 + g) * 36 + 8 * k0 + tg;
            uint2 A01 = pw[0];
            uint2 A23 = pw[4];
            mma16(dv0, A01.x, A01.y, A23.x, A23.y, xB[4 * k0 + 0], xB[4 * k0 + 2]);
            mma16(dv1, A01.x, A01.y, A23.x, A23.y, xB[4 * k0 + 1], xB[4 * k0 + 3]);
        }
        // out columns 16mt..16mt+15: vT C-frags ARE the needed B-frags
        #pragma unroll
        for (int p = 0; p < 2; p++) {
            uint32_t b0 = h2u(dv0[2 * p], dv0[2 * p + 1]);
            uint32_t b1 = h2u(dv1[2 * p], dv1[2 * p + 1]);
            float od[4] = {};
            mma16(od, aa0, aa1, aa2, aa3, b0, b1);
            int cc = (2 * mt + p) * 8 + 2 * tg;
            float2 bb = *(const float2*)(sbv + cc);
            *(float2*)(og + g * 64 + cc) = make_float2(od[0] + bb.x, od[1] + bb.y);
            if (g < 6)
                *(float2*)(og + (g + 8) * 64 + cc) =
                    make_float2(od[2] + bb.x, od[3] + bb.y);
        }
    }
}

// ---------------------------------------------------------------------------
extern "C" void kernel_launch(void* const* d_in, const int* in_sizes, int n_in,
                              void* d_out, int out_size) {
    const float* x   = (const float*)d_in[0];
    const float* wc  = (const float*)d_in[1];
    const float* Wq  = (const float*)d_in[2];
    const float* bq  = (const float*)d_in[3];
    const float* Wk  = (const float*)d_in[4];
    const float* bk  = (const float*)d_in[5];
    const float* Wv  = (const float*)d_in[6];
    const float* bv  = (const float*)d_in[7];
    const float* lng = (const float*)d_in[8];
    const float* lnb = (const float*)d_in[9];
    float* out = (float*)d_out;

    cudaFuncSetAttribute(attn_kernel, cudaFuncAttributeMaxDynamicSharedMemorySize,
                         SMEM_BYTES);

    prep_kernel<<<12, 256>>>(Wq, bq, Wk, bk, Wv, wc);
    attn_kernel<<<8192, 32 * NW, SMEM_BYTES>>>(x, bv, lng, lnb, out);
}